// round 3
// baseline (speedup 1.0000x reference)
#include <cuda_runtime.h>
#include <cstdint>

// ---------------------------------------------------------------------------
// AggrEGATConv fused EGAT convolution.
//   output: res_n [N,16] followed by res_e [E,16], f32
// ---------------------------------------------------------------------------

#define MAXN 100000
#define MAXE 1600000

__device__ float g_fni [(size_t)MAXN * 64];
__device__ float g_fnj [(size_t)MAXN * 64];
__device__ float g_hsrc[(size_t)MAXN * 64];
__device__ float g_ex  [(size_t)MAXE * 4];
__device__ float g_z   [(size_t)MAXN * 4];

// ---- packed f32x2 helpers -------------------------------------------------
__device__ __forceinline__ unsigned long long pack2(float x, float y) {
    unsigned long long r;
    asm("mov.b64 %0, {%1, %2};"
        : "=l"(r) : "r"(__float_as_uint(x)), "r"(__float_as_uint(y)));
    return r;
}
__device__ __forceinline__ unsigned long long ffma2(unsigned long long a,
                                                    unsigned long long b,
                                                    unsigned long long c) {
    unsigned long long d;
    asm("fma.rn.f32x2 %0, %1, %2, %3;" : "=l"(d) : "l"(a), "l"(b), "l"(c));
    return d;
}
__device__ __forceinline__ float2 unpack2(unsigned long long v) {
    unsigned lo, hi;
    asm("mov.b64 {%0, %1}, %2;" : "=r"(lo), "=r"(hi) : "l"(v));
    return make_float2(__uint_as_float(lo), __uint_as_float(hi));
}
__device__ __forceinline__ void red_add_v4(float* p, float a, float b,
                                           float c, float d) {
    asm volatile("red.global.add.v4.f32 [%0], {%1, %2, %3, %4};"
                 :: "l"(p), "f"(a), "f"(b), "f"(c), "f"(d) : "memory");
}
__device__ __forceinline__ void red_add_v2(float* p, float a, float b) {
    asm volatile("red.global.add.v2.f32 [%0], {%1, %2};"
                 :: "l"(p), "f"(a), "f"(b) : "memory");
}

// ---------------------------------------------------------------------------
// Kernel 0: zero res_n and z.
// ---------------------------------------------------------------------------
__global__ void zero_kernel(float* __restrict__ out_n, int N) {
    int i = blockIdx.x * 256 + threadIdx.x;
    if (i < N * 16) out_n[i] = 0.0f;
    if (i < N * 4)  g_z[i]   = 0.0f;
}

// ---------------------------------------------------------------------------
// Kernel 1: node GEMMs (W_ni, W_nj, W_src+b).  One thread = one node.
// ---------------------------------------------------------------------------
__global__ __launch_bounds__(256)
void node_gemm(const float* __restrict__ nf,
               const float* __restrict__ Wni,
               const float* __restrict__ Wnj,
               const float* __restrict__ Wsrc,
               const float* __restrict__ bsrc,
               int N)
{
    __shared__ ulonglong2 sW[128 * 16];   // 32 KB pre-packed pairs
    __shared__ float      sb[64];

    const int which = blockIdx.y;
    const float* W = (which == 0) ? Wni : (which == 1) ? Wnj : Wsrc;
    float* out = (which == 0) ? g_fni : (which == 1) ? g_fnj : g_hsrc;

    const float4* Wv = (const float4*)W;
    for (int i = threadIdx.x; i < 2048; i += 256) {
        float4 w = Wv[i];
        ulonglong2 u;
        u.x = pack2(w.x, w.y);
        u.y = pack2(w.z, w.w);
        sW[i] = u;
    }
    if (threadIdx.x < 64)
        sb[threadIdx.x] = (which == 2) ? bsrc[threadIdx.x] : 0.0f;
    __syncthreads();

    const int n = blockIdx.x * 256 + threadIdx.x;
    if (n >= N) return;

    unsigned long long acc[32];
#pragma unroll
    for (int p = 0; p < 32; ++p) acc[p] = 0ull;

    const float4* xv = (const float4*)(nf + (size_t)n * 128);
#pragma unroll 4
    for (int k4 = 0; k4 < 32; ++k4) {
        float4 xq = xv[k4];
#pragma unroll
        for (int j = 0; j < 4; ++j) {
            float xs = (j == 0) ? xq.x : (j == 1) ? xq.y : (j == 2) ? xq.z : xq.w;
            unsigned long long xx = pack2(xs, xs);
            const int k = k4 * 4 + j;
#pragma unroll
            for (int q = 0; q < 16; ++q) {
                ulonglong2 w = sW[k * 16 + q];
                acc[2 * q]     = ffma2(xx, w.x, acc[2 * q]);
                acc[2 * q + 1] = ffma2(xx, w.y, acc[2 * q + 1]);
            }
        }
    }

    float* o = out + (size_t)n * 64;
#pragma unroll
    for (int p = 0; p < 32; ++p) {
        float2 v = unpack2(acc[p]);
        o[2 * p]     = v.x + sb[2 * p];
        o[2 * p + 1] = v.y + sb[2 * p + 1];
    }
}

// ---------------------------------------------------------------------------
// Kernel 2: edge pass 1.  8 lanes per edge (lane t owns cols 8t..8t+7).
//   GEMM uses k-pair f32x2: acc_c += (x2k,x2k+1)*(W[2k][c],W[2k+1][c]);
//   W staged in smem with XOR swizzle -> conflict-free LDS.128.
//   Epilogue gathers f_ni[src]/f_nj[dst] cooperatively (contiguous per edge).
// ---------------------------------------------------------------------------
__global__ __launch_bounds__(256)
void edge_main(const float* __restrict__ efeats,
               const int*   __restrict__ src,
               const int*   __restrict__ dst,
               const float* __restrict__ Wfij,
               const float* __restrict__ attn,
               const float* __restrict__ bias_e,
               float* __restrict__ out_e,
               int E)
{
    // sw2[kp*32 + swz(cpair)]: .x = f32x2(W[2kp][2cp],W[2kp+1][2cp]),
    //                          .y = same for col 2cp+1
    __shared__ ulonglong2 sw2[32 * 32];          // 16 KB
    __shared__ float s_x[32 * 68];               // 32 edges, stride 68 (8.5 KB)
    __shared__ float s_attn[64];
    __shared__ float s_bias[64];

    const int tid = threadIdx.x;

    // pack W with swizzle
    for (int idx = tid; idx < 1024; idx += 256) {
        const int kp = idx >> 5;
        const int cp = idx & 31;
        const int c0 = 2 * cp;
        ulonglong2 u;
        u.x = pack2(Wfij[(2 * kp) * 64 + c0],     Wfij[(2 * kp + 1) * 64 + c0]);
        u.y = pack2(Wfij[(2 * kp) * 64 + c0 + 1], Wfij[(2 * kp + 1) * 64 + c0 + 1]);
        sw2[kp * 32 + (cp ^ ((cp >> 2) & 7))] = u;
    }
    if (tid < 64) {
        s_attn[tid] = attn[tid];
        s_bias[tid] = bias_e[tid];
    }

    // stage efeats rows for the block's 32 edges (coalesced)
    const long long ebase = (long long)blockIdx.x * 32;
    {
        const float4* ef4 = (const float4*)efeats;
        for (int v = tid; v < 512; v += 256) {
            const int le = v >> 4;           // local edge
            const int ch = v & 15;           // float4 chunk
            float4 xq = make_float4(0.f, 0.f, 0.f, 0.f);
            if (ebase + le < E) xq = ef4[(ebase + le) * 16 + ch];
            *(float4*)(s_x + le * 68 + ch * 4) = xq;
        }
    }
    __syncthreads();

    const int lane = tid & 31;
    const int t    = lane & 7;                      // lane within edge-group
    const int le   = (tid >> 5) * 4 + (lane >> 3);  // local edge 0..31
    const long long e = ebase + le;
    if (e >= E) return;

    // x row into registers as k-pair f32x2 values
    ulonglong2 lx[16];
    {
        const ulonglong2* xr = (const ulonglong2*)(s_x + le * 68);
#pragma unroll
        for (int i = 0; i < 16; ++i) lx[i] = xr[i];
    }

    const int s = src[e];
    const int d = dst[e];

    unsigned long long acc[8];
#pragma unroll
    for (int i = 0; i < 8; ++i) acc[i] = 0ull;

#pragma unroll 8
    for (int kp = 0; kp < 32; ++kp) {
        const unsigned long long xx = (kp & 1) ? lx[kp >> 1].y : lx[kp >> 1].x;
        const int rb = kp * 32;
#pragma unroll
        for (int j = 0; j < 4; ++j) {
            const int cp = 4 * t + j;
            ulonglong2 w = sw2[rb + (cp ^ t)];      // (cp>>2)==t for this lane
            acc[2 * j]     = ffma2(xx, w.x, acc[2 * j]);
            acc[2 * j + 1] = ffma2(xx, w.y, acc[2 * j + 1]);
        }
    }

    // gather f_ni[s], f_nj[d]: this lane's 8 cols (contiguous 32B x2)
    const float4* av = (const float4*)(g_fni + (size_t)s * 64 + 8 * t);
    const float4* bv = (const float4*)(g_fnj + (size_t)d * 64 + 8 * t);
    float4 fa0 = av[0], fa1 = av[1];
    float4 fb0 = bv[0], fb1 = bv[1];
    float fa[8] = {fa0.x, fa0.y, fa0.z, fa0.w, fa1.x, fa1.y, fa1.z, fa1.w};
    float fb[8] = {fb0.x, fb0.y, fb0.z, fb0.w, fb1.x, fb1.y, fb1.z, fb1.w};

    float c[8];
    float lp = 0.0f;
#pragma unroll
    for (int i = 0; i < 8; ++i) {
        float2 v = unpack2(acc[i]);
        float cv = v.x + v.y + fa[i] + fb[i] + s_bias[8 * t + i];
        cv = (cv > 0.0f) ? cv : 0.01f * cv;
        c[i] = cv;
        lp += cv * s_attn[8 * t + i];
    }

    // head logit: lanes (2h,2h+1) hold head h halves
    lp += __shfl_xor_sync(0xffffffffu, lp, 1);

    // lane 0 of each 8-group gathers all 4 head logits, does exp + z red
    const int base = lane & ~7;
    float l0 = __shfl_sync(0xffffffffu, lp, base + 0);
    float l1 = __shfl_sync(0xffffffffu, lp, base + 2);
    float l2 = __shfl_sync(0xffffffffu, lp, base + 4);
    float l3 = __shfl_sync(0xffffffffu, lp, base + 6);
    if (t == 0) {
        float e0 = expf(l0), e1 = expf(l1), e2 = expf(l2), e3 = expf(l3);
        *(float4*)(g_ex + (size_t)e * 4) = make_float4(e0, e1, e2, e3);
        red_add_v4(&g_z[(size_t)d * 4], e0, e1, e2, e3);
    }

    // res_e: mean over heads -> reduce across lanes t, t^2, t^4, t^6
#pragma unroll
    for (int i = 0; i < 8; ++i) {
        c[i] += __shfl_xor_sync(0xffffffffu, c[i], 2);
        c[i] += __shfl_xor_sync(0xffffffffu, c[i], 4);
        c[i] *= 0.25f;
    }
    if (t < 2) {   // t=0 -> dims 0..7, t=1 -> dims 8..15
        float4* ov = (float4*)(out_e + (size_t)e * 16 + 8 * t);
        ov[0] = make_float4(c[0], c[1], c[2], c[3]);
        ov[1] = make_float4(c[4], c[5], c[6], c[7]);
    }
}

// ---------------------------------------------------------------------------
// Kernel 3: invert z once per (node, head)
// ---------------------------------------------------------------------------
__global__ void inv_z(int N) {
    int i = blockIdx.x * 256 + threadIdx.x;
    if (i < N * 4) g_z[i] = __frcp_rn(g_z[i]);
}

// ---------------------------------------------------------------------------
// Kernel 4: edge pass 2.  8 lanes/edge; lane t owns output dims 2t,2t+1.
//   a = ex * zinv[dst];  res_n[dst] += mean_h a_h * h_src[src,h]
// ---------------------------------------------------------------------------
__global__ __launch_bounds__(256)
void edge_aggr(const int* __restrict__ src,
               const int* __restrict__ dst,
               float* __restrict__ out_n,
               int E)
{
    const int tid  = threadIdx.x;
    const int lane = tid & 31;
    const int t    = lane & 7;
    const int le   = (tid >> 5) * 4 + (lane >> 3);
    const long long e = (long long)blockIdx.x * 32 + le;
    if (e >= E) return;

    const int s = src[e];
    const int d = dst[e];

    float4 ex4 = *(const float4*)(g_ex + (size_t)e * 4);   // group broadcast
    float4 zi4 = *(const float4*)(g_z  + (size_t)d * 4);
    const float a0 = 0.25f * ex4.x * zi4.x;
    const float a1 = 0.25f * ex4.y * zi4.y;
    const float a2 = 0.25f * ex4.z * zi4.z;
    const float a3 = 0.25f * ex4.w * zi4.w;

    const float* hr = g_hsrc + (size_t)s * 64 + 2 * t;
    float2 v0 = *(const float2*)(hr);
    float2 v1 = *(const float2*)(hr + 16);
    float2 v2 = *(const float2*)(hr + 32);
    float2 v3 = *(const float2*)(hr + 48);

    float m0 = a0 * v0.x + a1 * v1.x + a2 * v2.x + a3 * v3.x;
    float m1 = a0 * v0.y + a1 * v1.y + a2 * v2.y + a3 * v3.y;

    red_add_v2(out_n + (size_t)d * 16 + 2 * t, m0, m1);
}

// ---------------------------------------------------------------------------
extern "C" void kernel_launch(void* const* d_in, const int* in_sizes, int n_in,
                              void* d_out, int out_size)
{
    const float* nfeats = (const float*)d_in[0];
    const float* efeats = (const float*)d_in[1];
    const int*   src    = (const int*)  d_in[2];
    const int*   dst    = (const int*)  d_in[3];
    const float* Wni    = (const float*)d_in[4];
    const float* Wnj    = (const float*)d_in[5];
    const float* Wfij   = (const float*)d_in[6];
    const float* Wsrc   = (const float*)d_in[7];
    const float* bsrc   = (const float*)d_in[8];
    const float* attn   = (const float*)d_in[9];
    const float* biase  = (const float*)d_in[10];

    const int N = in_sizes[0] / 128;
    const int E = in_sizes[2];

    float* out_n = (float*)d_out;
    float* out_e = out_n + (size_t)N * 16;

    zero_kernel<<<(N * 16 + 255) / 256, 256>>>(out_n, N);

    dim3 g1((N + 255) / 256, 3);
    node_gemm<<<g1, 256>>>(nfeats, Wni, Wnj, Wsrc, bsrc, N);

    edge_main<<<(E + 31) / 32, 256>>>(efeats, src, dst, Wfij, attn, biase,
                                      out_e, E);

    inv_z<<<(N * 4 + 255) / 256, 256>>>(N);

    edge_aggr<<<(E + 31) / 32, 256>>>(src, dst, out_n, E);
}

// round 4
// speedup vs baseline: 1.3190x; 1.3190x over previous
#include <cuda_runtime.h>
#include <cstdint>

// ---------------------------------------------------------------------------
// AggrEGATConv fused EGAT convolution.
//   output: res_n [N,16] followed by res_e [E,16], f32
// ---------------------------------------------------------------------------

#define MAXN 100000
#define MAXE 1600000

__device__ float g_fni [(size_t)MAXN * 64];
__device__ float g_fnj [(size_t)MAXN * 64];
__device__ float g_hsrc[(size_t)MAXN * 64];
__device__ float g_ex  [(size_t)MAXE * 4];
__device__ float g_z   [(size_t)MAXN * 4];

// ---- packed f32x2 helpers -------------------------------------------------
__device__ __forceinline__ unsigned long long pack2(float x, float y) {
    unsigned long long r;
    asm("mov.b64 %0, {%1, %2};"
        : "=l"(r) : "r"(__float_as_uint(x)), "r"(__float_as_uint(y)));
    return r;
}
__device__ __forceinline__ unsigned long long ffma2(unsigned long long a,
                                                    unsigned long long b,
                                                    unsigned long long c) {
    unsigned long long d;
    asm("fma.rn.f32x2 %0, %1, %2, %3;" : "=l"(d) : "l"(a), "l"(b), "l"(c));
    return d;
}
__device__ __forceinline__ void red_add_v4(float* p, float a, float b,
                                           float c, float d) {
    asm volatile("red.global.add.v4.f32 [%0], {%1, %2, %3, %4};"
                 :: "l"(p), "f"(a), "f"(b), "f"(c), "f"(d) : "memory");
}
__device__ __forceinline__ void red_add_v2(float* p, float a, float b) {
    asm volatile("red.global.add.v2.f32 [%0], {%1, %2};"
                 :: "l"(p), "f"(a), "f"(b) : "memory");
}

// ---------------------------------------------------------------------------
// Kernel 0: zero res_n and z.
// ---------------------------------------------------------------------------
__global__ void zero_kernel(float* __restrict__ out_n, int N) {
    int i = blockIdx.x * 256 + threadIdx.x;
    if (i < N * 16) out_n[i] = 0.0f;
    if (i < N * 4)  g_z[i]   = 0.0f;
}

// ---------------------------------------------------------------------------
// Kernel 1: node GEMMs (W_ni, W_nj, W_src+b).  One thread = one node.
// Broadcast smem W (pre-packed f32x2 pairs).
// ---------------------------------------------------------------------------
__global__ __launch_bounds__(256)
void node_gemm(const float* __restrict__ nf,
               const float* __restrict__ Wni,
               const float* __restrict__ Wnj,
               const float* __restrict__ Wsrc,
               const float* __restrict__ bsrc,
               int N)
{
    __shared__ ulonglong2 sW[128 * 16];   // 32 KB
    __shared__ float      sb[64];

    const int which = blockIdx.y;
    const float* W = (which == 0) ? Wni : (which == 1) ? Wnj : Wsrc;
    float* out = (which == 0) ? g_fni : (which == 1) ? g_fnj : g_hsrc;

    const float4* Wv = (const float4*)W;
    for (int i = threadIdx.x; i < 2048; i += 256) {
        float4 w = Wv[i];
        ulonglong2 u;
        u.x = pack2(w.x, w.y);
        u.y = pack2(w.z, w.w);
        sW[i] = u;
    }
    if (threadIdx.x < 64)
        sb[threadIdx.x] = (which == 2) ? bsrc[threadIdx.x] : 0.0f;
    __syncthreads();

    const int n = blockIdx.x * 256 + threadIdx.x;
    if (n >= N) return;

    unsigned long long acc[32];
#pragma unroll
    for (int p = 0; p < 32; ++p) acc[p] = 0ull;

    const float4* xv = (const float4*)(nf + (size_t)n * 128);
#pragma unroll 4
    for (int k4 = 0; k4 < 32; ++k4) {
        float4 xq = xv[k4];
#pragma unroll
        for (int j = 0; j < 4; ++j) {
            float xs = (j == 0) ? xq.x : (j == 1) ? xq.y : (j == 2) ? xq.z : xq.w;
            unsigned long long xx = pack2(xs, xs);
            const int k = k4 * 4 + j;
#pragma unroll
            for (int q = 0; q < 16; ++q) {
                ulonglong2 w = sW[k * 16 + q];
                acc[2 * q]     = ffma2(xx, w.x, acc[2 * q]);
                acc[2 * q + 1] = ffma2(xx, w.y, acc[2 * q + 1]);
            }
        }
    }

    float* o = out + (size_t)n * 64;
#pragma unroll
    for (int p = 0; p < 32; ++p) {
        float2 v = *(float2*)&acc[p];
        o[2 * p]     = v.x + sb[2 * p];
        o[2 * p + 1] = v.y + sb[2 * p + 1];
    }
}

// ---------------------------------------------------------------------------
// Kernel 2: edge pass 1.  One thread = one edge (GEMM, broadcast W),
// then per-warp transposed epilogue:
//   - stage x rows coalesced into per-warp smem buffer
//   - GEMM from smem (conflict-free), acc written back into same buffer
//   - 32 rounds: lane l owns cols 2l,2l+1 of edge r; fni/fnj gathered as
//     contiguous 256B warp reads; shuffle-reduce logits + head-mean res_e.
// ---------------------------------------------------------------------------
__global__ __launch_bounds__(256)
void edge_main(const float* __restrict__ efeats,
               const int*   __restrict__ src,
               const int*   __restrict__ dst,
               const float* __restrict__ Wfij,
               const float* __restrict__ attn,
               const float* __restrict__ bias_e,
               float* __restrict__ out_e,
               int E)
{
    extern __shared__ char dyns[];
    ulonglong2* sW   = (ulonglong2*)dyns;                      // 16384 B
    float* accbuf    = (float*)(dyns + 16384);                 // 8*32*68*4 B
    float* s_attn    = (float*)(dyns + 16384 + 69632);         // 256 B
    float* s_bias    = s_attn + 64;                            // 256 B

    const int tid  = threadIdx.x;
    const int lane = tid & 31;
    const int w    = tid >> 5;

    // pack W (broadcast layout, same as node_gemm)
    const float4* Wv = (const float4*)Wfij;
    for (int i = tid; i < 1024; i += 256) {
        float4 ww = Wv[i];
        ulonglong2 u;
        u.x = pack2(ww.x, ww.y);
        u.y = pack2(ww.z, ww.w);
        sW[i] = u;
    }
    if (tid < 64) {
        s_attn[tid] = attn[tid];
        s_bias[tid] = bias_e[tid];
    }

    const long long ebase_w = (long long)blockIdx.x * 256 + w * 32;
    const long long e = ebase_w + lane;

    // stage this warp's 32 efeats rows, coalesced (512B contiguous / instr)
    float* buf = accbuf + w * (32 * 68);
    {
        const float4* ef4 = (const float4*)efeats;
#pragma unroll
        for (int i = 0; i < 16; ++i) {
            int idx = i * 32 + lane;            // 0..511
            int row = idx >> 4;
            int ch  = idx & 15;
            long long er = ebase_w + row;
            float4 v = make_float4(0.f, 0.f, 0.f, 0.f);
            if (er < E) v = ef4[er * 16 + ch];
            *(float4*)(buf + row * 68 + ch * 4) = v;
        }
    }
    __syncthreads();    // sW + staged x visible

    int myS = 0, myD = 0;
    if (e < E) { myS = src[e]; myD = dst[e]; }

    // GEMM: x from own smem row (conflict-free LDS.128), W broadcast
    unsigned long long acc[32];
#pragma unroll
    for (int p = 0; p < 32; ++p) acc[p] = 0ull;

    const float* xrow = buf + lane * 68;
#pragma unroll 4
    for (int k4 = 0; k4 < 16; ++k4) {
        float4 xq = *(const float4*)(xrow + k4 * 4);
#pragma unroll
        for (int j = 0; j < 4; ++j) {
            float xs = (j == 0) ? xq.x : (j == 1) ? xq.y : (j == 2) ? xq.z : xq.w;
            unsigned long long xx = pack2(xs, xs);
            const int k = k4 * 4 + j;
#pragma unroll
            for (int q = 0; q < 16; ++q) {
                ulonglong2 ww = sW[k * 16 + q];
                acc[2 * q]     = ffma2(xx, ww.x, acc[2 * q]);
                acc[2 * q + 1] = ffma2(xx, ww.y, acc[2 * q + 1]);
            }
        }
    }

    // write acc back into own row (x fully consumed; thread-private row)
#pragma unroll
    for (int i = 0; i < 16; ++i) {
        ulonglong2 u; u.x = acc[2 * i]; u.y = acc[2 * i + 1];
        *(ulonglong2*)(xrow + i * 4) = u;
    }
    __syncwarp();

    // transposed epilogue: lane l owns cols 2l, 2l+1
    const float b0 = s_bias[2 * lane];
    const float b1 = s_bias[2 * lane + 1];
    const float a0 = s_attn[2 * lane];
    const float a1 = s_attn[2 * lane + 1];

#pragma unroll 4
    for (int r = 0; r < 32; ++r) {
        long long e_r = ebase_w + r;
        if (e_r >= E) break;                    // uniform across warp
        const int s_r = __shfl_sync(0xffffffffu, myS, r);
        const int d_r = __shfl_sync(0xffffffffu, myD, r);

        float2 fa = *(const float2*)(g_fni + (size_t)s_r * 64 + 2 * lane);
        float2 fb = *(const float2*)(g_fnj + (size_t)d_r * 64 + 2 * lane);
        float2 ac = *(const float2*)(buf + r * 68 + 2 * lane);

        float y0 = ac.x + fa.x + fb.x + b0;
        float y1 = ac.y + fa.y + fb.y + b1;
        y0 = (y0 > 0.0f) ? y0 : 0.01f * y0;
        y1 = (y1 > 0.0f) ? y1 : 0.01f * y1;

        // per-head logit: reduce within 8-lane group (head = lane>>3)
        float lp = y0 * a0 + y1 * a1;
        lp += __shfl_xor_sync(0xffffffffu, lp, 4);
        lp += __shfl_xor_sync(0xffffffffu, lp, 2);
        lp += __shfl_xor_sync(0xffffffffu, lp, 1);

        // res_e: mean over heads (cols differ by 16 -> lanes differ by 8)
        y0 += __shfl_xor_sync(0xffffffffu, y0, 8);
        y0 += __shfl_xor_sync(0xffffffffu, y0, 16);
        y1 += __shfl_xor_sync(0xffffffffu, y1, 8);
        y1 += __shfl_xor_sync(0xffffffffu, y1, 16);

        float l1v = __shfl_sync(0xffffffffu, lp, 8);
        float l2v = __shfl_sync(0xffffffffu, lp, 16);
        float l3v = __shfl_sync(0xffffffffu, lp, 24);

        if (lane < 8)
            *(float2*)(out_e + (size_t)e_r * 16 + 2 * lane) =
                make_float2(0.25f * y0, 0.25f * y1);

        if (lane == 0) {
            float e0 = expf(lp),  e1 = expf(l1v);
            float e2 = expf(l2v), e3 = expf(l3v);
            *(float4*)(g_ex + (size_t)e_r * 4) = make_float4(e0, e1, e2, e3);
            red_add_v4(&g_z[(size_t)d_r * 4], e0, e1, e2, e3);
        }
    }
}

// ---------------------------------------------------------------------------
// Kernel 3: invert z once per (node, head)
// ---------------------------------------------------------------------------
__global__ void inv_z(int N) {
    int i = blockIdx.x * 256 + threadIdx.x;
    if (i < N * 4) g_z[i] = __frcp_rn(g_z[i]);
}

// ---------------------------------------------------------------------------
// Kernel 4: edge pass 2.  8 lanes/edge; lane t owns output dims 2t,2t+1.
// ---------------------------------------------------------------------------
__global__ __launch_bounds__(256)
void edge_aggr(const int* __restrict__ src,
               const int* __restrict__ dst,
               float* __restrict__ out_n,
               int E)
{
    const int tid  = threadIdx.x;
    const int lane = tid & 31;
    const int t    = lane & 7;
    const int le   = (tid >> 5) * 4 + (lane >> 3);
    const long long e = (long long)blockIdx.x * 32 + le;
    if (e >= E) return;

    const int s = src[e];
    const int d = dst[e];

    float4 ex4 = *(const float4*)(g_ex + (size_t)e * 4);
    float4 zi4 = *(const float4*)(g_z  + (size_t)d * 4);
    const float a0 = 0.25f * ex4.x * zi4.x;
    const float a1 = 0.25f * ex4.y * zi4.y;
    const float a2 = 0.25f * ex4.z * zi4.z;
    const float a3 = 0.25f * ex4.w * zi4.w;

    const float* hr = g_hsrc + (size_t)s * 64 + 2 * t;
    float2 v0 = *(const float2*)(hr);
    float2 v1 = *(const float2*)(hr + 16);
    float2 v2 = *(const float2*)(hr + 32);
    float2 v3 = *(const float2*)(hr + 48);

    float m0 = a0 * v0.x + a1 * v1.x + a2 * v2.x + a3 * v3.x;
    float m1 = a0 * v0.y + a1 * v1.y + a2 * v2.y + a3 * v3.y;

    red_add_v2(out_n + (size_t)d * 16 + 2 * t, m0, m1);
}

// ---------------------------------------------------------------------------
extern "C" void kernel_launch(void* const* d_in, const int* in_sizes, int n_in,
                              void* d_out, int out_size)
{
    const float* nfeats = (const float*)d_in[0];
    const float* efeats = (const float*)d_in[1];
    const int*   src    = (const int*)  d_in[2];
    const int*   dst    = (const int*)  d_in[3];
    const float* Wni    = (const float*)d_in[4];
    const float* Wnj    = (const float*)d_in[5];
    const float* Wfij   = (const float*)d_in[6];
    const float* Wsrc   = (const float*)d_in[7];
    const float* bsrc   = (const float*)d_in[8];
    const float* attn   = (const float*)d_in[9];
    const float* biase  = (const float*)d_in[10];

    const int N = in_sizes[0] / 128;
    const int E = in_sizes[2];

    float* out_n = (float*)d_out;
    float* out_e = out_n + (size_t)N * 16;

    static int smem_set = 0;
    const int EM_SMEM = 16384 + 69632 + 512;   // 86528 B
    if (!smem_set) {
        cudaFuncSetAttribute(edge_main,
                             cudaFuncAttributeMaxDynamicSharedMemorySize,
                             EM_SMEM);
        smem_set = 1;
    }

    zero_kernel<<<(N * 16 + 255) / 256, 256>>>(out_n, N);

    dim3 g1((N + 255) / 256, 3);
    node_gemm<<<g1, 256>>>(nfeats, Wni, Wnj, Wsrc, bsrc, N);

    edge_main<<<(E + 255) / 256, 256, EM_SMEM>>>(efeats, src, dst, Wfij,
                                                 attn, biase, out_e, E);

    inv_z<<<(N * 4 + 255) / 256, 256>>>(N);

    edge_aggr<<<(E + 31) / 32, 256>>>(src, dst, out_n, E);
}

// round 6
// speedup vs baseline: 1.3572x; 1.0290x over previous
#include <cuda_runtime.h>
#include <cuda_bf16.h>
#include <cstdint>

// ---------------------------------------------------------------------------
// AggrEGATConv fused EGAT convolution.
//   output: res_n [N,16] followed by res_e [E,16], f32
// ---------------------------------------------------------------------------

#define MAXN 100000
#define MAXE 1600000

__device__ float g_fni [(size_t)MAXN * 64];
__device__ float g_fnj [(size_t)MAXN * 64];
__device__ float g_hsrc[(size_t)MAXN * 64];
__device__ float g_ex  [(size_t)MAXE * 4];
__device__ float g_z   [(size_t)MAXN * 4];
// W_fij split into bf16 hi/lo, transposed (wt[n][k]), packed as (k,k+1) u32
__device__ unsigned g_wth[64 * 32];
__device__ unsigned g_wtl[64 * 32];

// ---- helpers ---------------------------------------------------------------
__device__ __forceinline__ unsigned long long pack2(float x, float y) {
    unsigned long long r;
    asm("mov.b64 %0, {%1, %2};"
        : "=l"(r) : "r"(__float_as_uint(x)), "r"(__float_as_uint(y)));
    return r;
}
__device__ __forceinline__ unsigned long long ffma2(unsigned long long a,
                                                    unsigned long long b,
                                                    unsigned long long c) {
    unsigned long long d;
    asm("fma.rn.f32x2 %0, %1, %2, %3;" : "=l"(d) : "l"(a), "l"(b), "l"(c));
    return d;
}
__device__ __forceinline__ void red_add_v4(float* p, float a, float b,
                                           float c, float d) {
    asm volatile("red.global.add.v4.f32 [%0], {%1, %2, %3, %4};"
                 :: "l"(p), "f"(a), "f"(b), "f"(c), "f"(d) : "memory");
}
__device__ __forceinline__ void red_add_v2(float* p, float a, float b) {
    asm volatile("red.global.add.v2.f32 [%0], {%1, %2};"
                 :: "l"(p), "f"(a), "f"(b) : "memory");
}
__device__ __forceinline__ unsigned bf16pack(float lo_elem, float hi_elem) {
    unsigned short ulo = __bfloat16_as_ushort(__float2bfloat16(lo_elem));
    unsigned short uhi = __bfloat16_as_ushort(__float2bfloat16(hi_elem));
    return (unsigned)ulo | ((unsigned)uhi << 16);
}
__device__ __forceinline__ float bf16residual(float x) {
    return x - __bfloat162float(__float2bfloat16(x));
}
__device__ __forceinline__ void mma16816(float& d0, float& d1, float& d2,
                                         float& d3, unsigned a0, unsigned a1,
                                         unsigned a2, unsigned a3,
                                         unsigned b0, unsigned b1) {
    asm volatile(
        "mma.sync.aligned.m16n8k16.row.col.f32.bf16.bf16.f32 "
        "{%0,%1,%2,%3}, {%4,%5,%6,%7}, {%8,%9}, {%0,%1,%2,%3};"
        : "+f"(d0), "+f"(d1), "+f"(d2), "+f"(d3)
        : "r"(a0), "r"(a1), "r"(a2), "r"(a3), "r"(b0), "r"(b1));
}

// x staging stride in words (must be EVEN for uint2 alignment)
#define XS 34

// ---------------------------------------------------------------------------
// Kernel 0: zero res_n and z.
// ---------------------------------------------------------------------------
__global__ void zero_kernel(float* __restrict__ out_n, int N) {
    int i = blockIdx.x * 256 + threadIdx.x;
    if (i < N * 16) out_n[i] = 0.0f;
    if (i < N * 4)  g_z[i]   = 0.0f;
}

// ---------------------------------------------------------------------------
// Kernel W: split W_fij into bf16 hi/lo, transposed+packed for B fragments.
//   g_wth[n*32+kp] = (bf16(W[2kp][n]), bf16(W[2kp+1][n]))
// ---------------------------------------------------------------------------
__global__ void wsplit(const float* __restrict__ Wfij) {
    int j = blockIdx.x * 256 + threadIdx.x;   // 0..2047
    if (j >= 2048) return;
    int n  = j >> 5;
    int kp = j & 31;
    float w0 = Wfij[(2 * kp) * 64 + n];
    float w1 = Wfij[(2 * kp + 1) * 64 + n];
    g_wth[j] = bf16pack(w0, w1);
    g_wtl[j] = bf16pack(bf16residual(w0), bf16residual(w1));
}

// ---------------------------------------------------------------------------
// Kernel 1: node GEMMs (FFMA2 version).
// ---------------------------------------------------------------------------
__global__ __launch_bounds__(256)
void node_gemm(const float* __restrict__ nf,
               const float* __restrict__ Wni,
               const float* __restrict__ Wnj,
               const float* __restrict__ Wsrc,
               const float* __restrict__ bsrc,
               int N)
{
    __shared__ ulonglong2 sW[128 * 16];
    __shared__ float      sb[64];

    const int which = blockIdx.y;
    const float* W = (which == 0) ? Wni : (which == 1) ? Wnj : Wsrc;
    float* out = (which == 0) ? g_fni : (which == 1) ? g_fnj : g_hsrc;

    const float4* Wv = (const float4*)W;
    for (int i = threadIdx.x; i < 2048; i += 256) {
        float4 w = Wv[i];
        ulonglong2 u;
        u.x = pack2(w.x, w.y);
        u.y = pack2(w.z, w.w);
        sW[i] = u;
    }
    if (threadIdx.x < 64)
        sb[threadIdx.x] = (which == 2) ? bsrc[threadIdx.x] : 0.0f;
    __syncthreads();

    const int n = blockIdx.x * 256 + threadIdx.x;
    if (n >= N) return;

    unsigned long long acc[32];
#pragma unroll
    for (int p = 0; p < 32; ++p) acc[p] = 0ull;

    const float4* xv = (const float4*)(nf + (size_t)n * 128);
#pragma unroll 4
    for (int k4 = 0; k4 < 32; ++k4) {
        float4 xq = xv[k4];
#pragma unroll
        for (int j = 0; j < 4; ++j) {
            float xs = (j == 0) ? xq.x : (j == 1) ? xq.y : (j == 2) ? xq.z : xq.w;
            unsigned long long xx = pack2(xs, xs);
            const int k = k4 * 4 + j;
#pragma unroll
            for (int q = 0; q < 16; ++q) {
                ulonglong2 w = sW[k * 16 + q];
                acc[2 * q]     = ffma2(xx, w.x, acc[2 * q]);
                acc[2 * q + 1] = ffma2(xx, w.y, acc[2 * q + 1]);
            }
        }
    }

    float* o = out + (size_t)n * 64;
#pragma unroll
    for (int p = 0; p < 32; ++p) {
        float2 v = *(float2*)&acc[p];
        o[2 * p]     = v.x + sb[2 * p];
        o[2 * p + 1] = v.y + sb[2 * p + 1];
    }
}

// ---------------------------------------------------------------------------
// Kernel 2: edge pass 1 via tensor cores (bf16x3 split MMA).
//   Block = 256 thr = 8 warps; block tile = 128 edges; warp tile = 16 edges.
// ---------------------------------------------------------------------------
__global__ __launch_bounds__(256)
void edge_main(const float* __restrict__ efeats,
               const int*   __restrict__ src,
               const int*   __restrict__ dst,
               const float* __restrict__ attn,
               const float* __restrict__ bias_e,
               float* __restrict__ out_e,
               int E)
{
    extern __shared__ char dyns[];
    unsigned* s_wh = (unsigned*)dyns;                    // 64*33 u32
    unsigned* s_wl = s_wh + 64 * 33;
    unsigned* s_xh = s_wl + 64 * 33;                     // 128*XS u32
    unsigned* s_xl = s_xh + 128 * XS;
    float*    epi  = (float*)(s_xl + 128 * XS);          // 128*66 f32
    float*    s_attn = epi + 128 * 66;
    float*    s_bias = s_attn + 64;

    const int tid  = threadIdx.x;
    const int lane = tid & 31;
    const int w    = tid >> 5;

    // stage W frag words (stride 33, scalar access -> alignment fine)
    for (int j = tid; j < 2048; j += 256) {
        int n = j >> 5, kp = j & 31;
        s_wh[n * 33 + kp] = g_wth[j];
        s_wl[n * 33 + kp] = g_wtl[j];
    }
    if (tid < 64) {
        s_attn[tid] = attn[tid];
        s_bias[tid] = bias_e[tid];
    }

    // stage x: coalesced load, split to bf16 hi/lo, pack (k,k+1) pairs
    const long long eblk = (long long)blockIdx.x * 128;
    {
        const float4* ef4 = (const float4*)efeats;
#pragma unroll
        for (int i = 0; i < 8; ++i) {
            int idx = i * 256 + tid;             // 0..2047
            int e  = idx >> 4;                   // local edge
            int ch = idx & 15;                   // float4 chunk
            float4 v = make_float4(0.f, 0.f, 0.f, 0.f);
            if (eblk + e < E) v = ef4[(eblk + e) * 16 + ch];
            unsigned h0 = bf16pack(v.x, v.y);
            unsigned h1 = bf16pack(v.z, v.w);
            unsigned l0 = bf16pack(bf16residual(v.x), bf16residual(v.y));
            unsigned l1 = bf16pack(bf16residual(v.z), bf16residual(v.w));
            *(uint2*)(s_xh + e * XS + ch * 2) = make_uint2(h0, h1);
            *(uint2*)(s_xl + e * XS + ch * 2) = make_uint2(l0, l1);
        }
    }
    __syncthreads();

    const long long ewarp = eblk + w * 16;
    const int g = lane >> 2;       // group id
    const int q = lane & 3;        // thread in group

    int myS = 0, myD = 0;
    if (lane < 16 && ewarp + lane < E) {
        myS = src[ewarp + lane];
        myD = dst[ewarp + lane];
    }

    float acc[8][4];
#pragma unroll
    for (int nt = 0; nt < 8; ++nt)
#pragma unroll
        for (int i = 0; i < 4; ++i) acc[nt][i] = 0.0f;

    const unsigned* xh0 = s_xh + (w * 16 + g) * XS;
    const unsigned* xh8 = xh0 + 8 * XS;
    const unsigned* xl0 = s_xl + (w * 16 + g) * XS;
    const unsigned* xl8 = xl0 + 8 * XS;

#pragma unroll
    for (int kt = 0; kt < 4; ++kt) {
        const int kp = kt * 8 + q;
        unsigned ah0 = xh0[kp],     ah1 = xh8[kp];
        unsigned ah2 = xh0[kp + 4], ah3 = xh8[kp + 4];
        unsigned al0 = xl0[kp],     al1 = xl8[kp];
        unsigned al2 = xl0[kp + 4], al3 = xl8[kp + 4];
#pragma unroll
        for (int nt = 0; nt < 8; ++nt) {
            const unsigned* wb  = s_wh + (nt * 8 + g) * 33 + kp;
            const unsigned* wlb = s_wl + (nt * 8 + g) * 33 + kp;
            unsigned bh0 = wb[0],  bh1 = wb[4];
            unsigned bl0 = wlb[0], bl1 = wlb[4];
            mma16816(acc[nt][0], acc[nt][1], acc[nt][2], acc[nt][3],
                     ah0, ah1, ah2, ah3, bh0, bh1);
            mma16816(acc[nt][0], acc[nt][1], acc[nt][2], acc[nt][3],
                     ah0, ah1, ah2, ah3, bl0, bl1);
            mma16816(acc[nt][0], acc[nt][1], acc[nt][2], acc[nt][3],
                     al0, al1, al2, al3, bh0, bh1);
        }
    }

    // scatter fragments to per-warp epi buffer (stride 66, float2-aligned)
    float* epiw = epi + w * (16 * 66);
#pragma unroll
    for (int nt = 0; nt < 8; ++nt) {
        const int c = nt * 8 + 2 * q;
        *(float2*)(epiw + g * 66 + c)       = make_float2(acc[nt][0], acc[nt][1]);
        *(float2*)(epiw + (g + 8) * 66 + c) = make_float2(acc[nt][2], acc[nt][3]);
    }
    __syncwarp();

    // per-edge epilogue: lane l owns cols 2l, 2l+1
    const float b0 = s_bias[2 * lane];
    const float b1 = s_bias[2 * lane + 1];
    const float a0 = s_attn[2 * lane];
    const float a1 = s_attn[2 * lane + 1];

    for (int r = 0; r < 16; ++r) {
        long long e_r = ewarp + r;
        if (e_r >= E) break;                    // warp-uniform
        const int s_r = __shfl_sync(0xffffffffu, myS, r);
        const int d_r = __shfl_sync(0xffffffffu, myD, r);

        float2 fa = *(const float2*)(g_fni + (size_t)s_r * 64 + 2 * lane);
        float2 fb = *(const float2*)(g_fnj + (size_t)d_r * 64 + 2 * lane);
        float2 ac = *(const float2*)(epiw + r * 66 + 2 * lane);

        float y0 = ac.x + fa.x + fb.x + b0;
        float y1 = ac.y + fa.y + fb.y + b1;
        y0 = (y0 > 0.0f) ? y0 : 0.01f * y0;
        y1 = (y1 > 0.0f) ? y1 : 0.01f * y1;

        float lp = y0 * a0 + y1 * a1;
        lp += __shfl_xor_sync(0xffffffffu, lp, 4);
        lp += __shfl_xor_sync(0xffffffffu, lp, 2);
        lp += __shfl_xor_sync(0xffffffffu, lp, 1);

        y0 += __shfl_xor_sync(0xffffffffu, y0, 8);
        y0 += __shfl_xor_sync(0xffffffffu, y0, 16);
        y1 += __shfl_xor_sync(0xffffffffu, y1, 8);
        y1 += __shfl_xor_sync(0xffffffffu, y1, 16);

        float l1v = __shfl_sync(0xffffffffu, lp, 8);
        float l2v = __shfl_sync(0xffffffffu, lp, 16);
        float l3v = __shfl_sync(0xffffffffu, lp, 24);

        if (lane < 8)
            *(float2*)(out_e + (size_t)e_r * 16 + 2 * lane) =
                make_float2(0.25f * y0, 0.25f * y1);

        if (lane == 0) {
            float e0 = expf(lp),  e1 = expf(l1v);
            float e2 = expf(l2v), e3 = expf(l3v);
            *(float4*)(g_ex + (size_t)e_r * 4) = make_float4(e0, e1, e2, e3);
            red_add_v4(&g_z[(size_t)d_r * 4], e0, e1, e2, e3);
        }
    }
}

// ---------------------------------------------------------------------------
// Kernel 3: invert z once per (node, head)
// ---------------------------------------------------------------------------
__global__ void inv_z(int N) {
    int i = blockIdx.x * 256 + threadIdx.x;
    if (i < N * 4) g_z[i] = __frcp_rn(g_z[i]);
}

// ---------------------------------------------------------------------------
// Kernel 4: edge pass 2.
// ---------------------------------------------------------------------------
__global__ __launch_bounds__(256)
void edge_aggr(const int* __restrict__ src,
               const int* __restrict__ dst,
               float* __restrict__ out_n,
               int E)
{
    const int tid  = threadIdx.x;
    const int lane = tid & 31;
    const int t    = lane & 7;
    const int le   = (tid >> 5) * 4 + (lane >> 3);
    const long long e = (long long)blockIdx.x * 32 + le;
    if (e >= E) return;

    const int s = src[e];
    const int d = dst[e];

    float4 ex4 = *(const float4*)(g_ex + (size_t)e * 4);
    float4 zi4 = *(const float4*)(g_z  + (size_t)d * 4);
    const float a0 = 0.25f * ex4.x * zi4.x;
    const float a1 = 0.25f * ex4.y * zi4.y;
    const float a2 = 0.25f * ex4.z * zi4.z;
    const float a3 = 0.25f * ex4.w * zi4.w;

    const float* hr = g_hsrc + (size_t)s * 64 + 2 * t;
    float2 v0 = *(const float2*)(hr);
    float2 v1 = *(const float2*)(hr + 16);
    float2 v2 = *(const float2*)(hr + 32);
    float2 v3 = *(const float2*)(hr + 48);

    float m0 = a0 * v0.x + a1 * v1.x + a2 * v2.x + a3 * v3.x;
    float m1 = a0 * v0.y + a1 * v1.y + a2 * v2.y + a3 * v3.y;

    red_add_v2(out_n + (size_t)d * 16 + 2 * t, m0, m1);
}

// ---------------------------------------------------------------------------
extern "C" void kernel_launch(void* const* d_in, const int* in_sizes, int n_in,
                              void* d_out, int out_size)
{
    const float* nfeats = (const float*)d_in[0];
    const float* efeats = (const float*)d_in[1];
    const int*   src    = (const int*)  d_in[2];
    const int*   dst    = (const int*)  d_in[3];
    const float* Wni    = (const float*)d_in[4];
    const float* Wnj    = (const float*)d_in[5];
    const float* Wfij   = (const float*)d_in[6];
    const float* Wsrc   = (const float*)d_in[7];
    const float* bsrc   = (const float*)d_in[8];
    const float* attn   = (const float*)d_in[9];
    const float* biase  = (const float*)d_in[10];

    const int N = in_sizes[0] / 128;
    const int E = in_sizes[2];

    float* out_n = (float*)d_out;
    float* out_e = out_n + (size_t)N * 16;

    static int smem_set = 0;
    const int EM_SMEM = (64 * 33 * 2 + 128 * XS * 2) * 4 + 128 * 66 * 4 + 512;
    if (!smem_set) {
        cudaFuncSetAttribute(edge_main,
                             cudaFuncAttributeMaxDynamicSharedMemorySize,
                             EM_SMEM);
        smem_set = 1;
    }

    // launch order chosen so index 3 (the one ncu profiles) = edge_main
    zero_kernel<<<(N * 16 + 255) / 256, 256>>>(out_n, N);

    wsplit<<<8, 256>>>(Wfij);

    dim3 g1((N + 255) / 256, 3);
    node_gemm<<<g1, 256>>>(nfeats, Wni, Wnj, Wsrc, bsrc, N);

    edge_main<<<(E + 127) / 128, 256, EM_SMEM>>>(efeats, src, dst,
                                                 attn, biase, out_e, E);

    inv_z<<<(N * 4 + 255) / 256, 256>>>(N);

    edge_aggr<<<(E + 31) / 32, 256>>>(src, dst, out_n, E);
}

// round 7
// speedup vs baseline: 1.9847x; 1.4624x over previous
#include <cuda_runtime.h>
#include <cuda_bf16.h>
#include <cstdint>

// ---------------------------------------------------------------------------
// AggrEGATConv fused EGAT convolution.
//   output: res_n [N,16] followed by res_e [E,16], f32
// ---------------------------------------------------------------------------

#define MAXN 100000
#define MAXE 1600000

__device__ float g_fni [(size_t)MAXN * 64];
__device__ float g_fnj [(size_t)MAXN * 64];
__device__ float g_hsrc[(size_t)MAXN * 64];
__device__ float g_ex  [(size_t)MAXE * 4];
__device__ float g_z   [(size_t)MAXN * 4];
// W_fij split into bf16 hi/lo, transposed (wt[n][k]), packed as (k,k+1) u32
__device__ unsigned g_wth[64 * 32];
__device__ unsigned g_wtl[64 * 32];

// ---- helpers ---------------------------------------------------------------
__device__ __forceinline__ unsigned long long pack2(float x, float y) {
    unsigned long long r;
    asm("mov.b64 %0, {%1, %2};"
        : "=l"(r) : "r"(__float_as_uint(x)), "r"(__float_as_uint(y)));
    return r;
}
__device__ __forceinline__ unsigned long long ffma2(unsigned long long a,
                                                    unsigned long long b,
                                                    unsigned long long c) {
    unsigned long long d;
    asm("fma.rn.f32x2 %0, %1, %2, %3;" : "=l"(d) : "l"(a), "l"(b), "l"(c));
    return d;
}
__device__ __forceinline__ void red_add_v4(float* p, float a, float b,
                                           float c, float d) {
    asm volatile("red.global.add.v4.f32 [%0], {%1, %2, %3, %4};"
                 :: "l"(p), "f"(a), "f"(b), "f"(c), "f"(d) : "memory");
}
__device__ __forceinline__ void red_add_v2(float* p, float a, float b) {
    asm volatile("red.global.add.v2.f32 [%0], {%1, %2};"
                 :: "l"(p), "f"(a), "f"(b) : "memory");
}
__device__ __forceinline__ unsigned bf16pack(float lo_elem, float hi_elem) {
    unsigned short ulo = __bfloat16_as_ushort(__float2bfloat16(lo_elem));
    unsigned short uhi = __bfloat16_as_ushort(__float2bfloat16(hi_elem));
    return (unsigned)ulo | ((unsigned)uhi << 16);
}
__device__ __forceinline__ float bf16residual(float x) {
    return x - __bfloat162float(__float2bfloat16(x));
}
__device__ __forceinline__ void mma16816(float& d0, float& d1, float& d2,
                                         float& d3, unsigned a0, unsigned a1,
                                         unsigned a2, unsigned a3,
                                         unsigned b0, unsigned b1) {
    asm volatile(
        "mma.sync.aligned.m16n8k16.row.col.f32.bf16.bf16.f32 "
        "{%0,%1,%2,%3}, {%4,%5,%6,%7}, {%8,%9}, {%0,%1,%2,%3};"
        : "+f"(d0), "+f"(d1), "+f"(d2), "+f"(d3)
        : "r"(a0), "r"(a1), "r"(a2), "r"(a3), "r"(b0), "r"(b1));
}

// strides (words). 36 mod 32 == 4 -> conflict-free fragment loads; even ->
// uint2-aligned. Per-warp x region (hi+lo) = 16*36*2 = 1152 words; the
// epilogue buffer (16*66 = 1056 words) aliases it after the MMA loop.
#define XS     36
#define WS     36
#define WREG   1152

// ---------------------------------------------------------------------------
// Kernel 0: zero res_n and z.
// ---------------------------------------------------------------------------
__global__ void zero_kernel(float* __restrict__ out_n, int N) {
    int i = blockIdx.x * 256 + threadIdx.x;
    if (i < N * 16) out_n[i] = 0.0f;
    if (i < N * 4)  g_z[i]   = 0.0f;
}

// ---------------------------------------------------------------------------
// Kernel W: split W_fij into bf16 hi/lo, transposed+packed for B fragments.
// ---------------------------------------------------------------------------
__global__ void wsplit(const float* __restrict__ Wfij) {
    int j = blockIdx.x * 256 + threadIdx.x;   // 0..2047
    if (j >= 2048) return;
    int n  = j >> 5;
    int kp = j & 31;
    float w0 = Wfij[(2 * kp) * 64 + n];
    float w1 = Wfij[(2 * kp + 1) * 64 + n];
    g_wth[j] = bf16pack(w0, w1);
    g_wtl[j] = bf16pack(bf16residual(w0), bf16residual(w1));
}

// ---------------------------------------------------------------------------
// Kernel 1: node GEMMs (FFMA2 version, unchanged).
// ---------------------------------------------------------------------------
__global__ __launch_bounds__(256)
void node_gemm(const float* __restrict__ nf,
               const float* __restrict__ Wni,
               const float* __restrict__ Wnj,
               const float* __restrict__ Wsrc,
               const float* __restrict__ bsrc,
               int N)
{
    __shared__ ulonglong2 sW[128 * 16];
    __shared__ float      sb[64];

    const int which = blockIdx.y;
    const float* W = (which == 0) ? Wni : (which == 1) ? Wnj : Wsrc;
    float* out = (which == 0) ? g_fni : (which == 1) ? g_fnj : g_hsrc;

    const float4* Wv = (const float4*)W;
    for (int i = threadIdx.x; i < 2048; i += 256) {
        float4 w = Wv[i];
        ulonglong2 u;
        u.x = pack2(w.x, w.y);
        u.y = pack2(w.z, w.w);
        sW[i] = u;
    }
    if (threadIdx.x < 64)
        sb[threadIdx.x] = (which == 2) ? bsrc[threadIdx.x] : 0.0f;
    __syncthreads();

    const int n = blockIdx.x * 256 + threadIdx.x;
    if (n >= N) return;

    unsigned long long acc[32];
#pragma unroll
    for (int p = 0; p < 32; ++p) acc[p] = 0ull;

    const float4* xv = (const float4*)(nf + (size_t)n * 128);
#pragma unroll 4
    for (int k4 = 0; k4 < 32; ++k4) {
        float4 xq = xv[k4];
#pragma unroll
        for (int j = 0; j < 4; ++j) {
            float xs = (j == 0) ? xq.x : (j == 1) ? xq.y : (j == 2) ? xq.z : xq.w;
            unsigned long long xx = pack2(xs, xs);
            const int k = k4 * 4 + j;
#pragma unroll
            for (int q = 0; q < 16; ++q) {
                ulonglong2 w = sW[k * 16 + q];
                acc[2 * q]     = ffma2(xx, w.x, acc[2 * q]);
                acc[2 * q + 1] = ffma2(xx, w.y, acc[2 * q + 1]);
            }
        }
    }

    float* o = out + (size_t)n * 64;
#pragma unroll
    for (int p = 0; p < 32; ++p) {
        float2 v = *(float2*)&acc[p];
        o[2 * p]     = v.x + sb[2 * p];
        o[2 * p + 1] = v.y + sb[2 * p + 1];
    }
}

// ---------------------------------------------------------------------------
// Kernel 2: edge pass 1 via tensor cores (bf16x3 split MMA).
//   8 warps/block; 128 edges/block; 16 edges/warp-tile.
//   smem: W(hi/lo, stride 36) + per-warp x(hi/lo, stride 36) which is
//   reused as the per-warp epilogue buffer after the MMA loop.
// ---------------------------------------------------------------------------
__global__ __launch_bounds__(256, 4)
void edge_main(const float* __restrict__ efeats,
               const int*   __restrict__ src,
               const int*   __restrict__ dst,
               const float* __restrict__ attn,
               const float* __restrict__ bias_e,
               float* __restrict__ out_e,
               int E)
{
    extern __shared__ char dyns[];
    unsigned* s_wh = (unsigned*)dyns;                    // 64*WS u32
    unsigned* s_wl = s_wh + 64 * WS;                     // 64*WS u32
    unsigned* s_x  = s_wl + 64 * WS;                     // 8 * WREG u32
    float*    s_attn = (float*)(s_x + 8 * WREG);
    float*    s_bias = s_attn + 64;

    const int tid  = threadIdx.x;
    const int lane = tid & 31;
    const int w    = tid >> 5;

    // stage W frag words
    for (int j = tid; j < 2048; j += 256) {
        int n = j >> 5, kp = j & 31;
        s_wh[n * WS + kp] = g_wth[j];
        s_wl[n * WS + kp] = g_wtl[j];
    }
    if (tid < 64) {
        s_attn[tid] = attn[tid];
        s_bias[tid] = bias_e[tid];
    }

    // stage x: coalesced load, bf16 hi/lo split, per-warp regions
    const long long eblk = (long long)blockIdx.x * 128;
    {
        const float4* ef4 = (const float4*)efeats;
#pragma unroll
        for (int i = 0; i < 8; ++i) {
            int idx = i * 256 + tid;             // 0..2047
            int e  = idx >> 4;                   // local edge 0..127
            int ch = idx & 15;                   // float4 chunk
            float4 v = make_float4(0.f, 0.f, 0.f, 0.f);
            if (eblk + e < E) v = ef4[(eblk + e) * 16 + ch];
            unsigned h0 = bf16pack(v.x, v.y);
            unsigned h1 = bf16pack(v.z, v.w);
            unsigned l0 = bf16pack(bf16residual(v.x), bf16residual(v.y));
            unsigned l1 = bf16pack(bf16residual(v.z), bf16residual(v.w));
            unsigned* base = s_x + (e >> 4) * WREG + (e & 15) * XS + ch * 2;
            *(uint2*)(base)            = make_uint2(h0, h1);
            *(uint2*)(base + 16 * XS)  = make_uint2(l0, l1);
        }
    }
    __syncthreads();

    const long long ewarp = eblk + w * 16;
    const int g = lane >> 2;       // group id
    const int q = lane & 3;        // thread in group

    int myS = 0, myD = 0;
    if (lane < 16 && ewarp + lane < E) {
        myS = src[ewarp + lane];
        myD = dst[ewarp + lane];
    }

    float acc[8][4];
#pragma unroll
    for (int nt = 0; nt < 8; ++nt)
#pragma unroll
        for (int i = 0; i < 4; ++i) acc[nt][i] = 0.0f;

    const unsigned* xh0 = s_x + w * WREG + g * XS;
    const unsigned* xh8 = xh0 + 8 * XS;
    const unsigned* xl0 = xh0 + 16 * XS;
    const unsigned* xl8 = xl0 + 8 * XS;

#pragma unroll
    for (int kt = 0; kt < 4; ++kt) {
        const int kp = kt * 8 + q;
        unsigned ah0 = xh0[kp],     ah1 = xh8[kp];
        unsigned ah2 = xh0[kp + 4], ah3 = xh8[kp + 4];
        unsigned al0 = xl0[kp],     al1 = xl8[kp];
        unsigned al2 = xl0[kp + 4], al3 = xl8[kp + 4];
#pragma unroll
        for (int nt = 0; nt < 8; ++nt) {
            const unsigned* wb  = s_wh + (nt * 8 + g) * WS + kp;
            const unsigned* wlb = s_wl + (nt * 8 + g) * WS + kp;
            unsigned bh0 = wb[0],  bh1 = wb[4];
            unsigned bl0 = wlb[0], bl1 = wlb[4];
            mma16816(acc[nt][0], acc[nt][1], acc[nt][2], acc[nt][3],
                     ah0, ah1, ah2, ah3, bh0, bh1);
            mma16816(acc[nt][0], acc[nt][1], acc[nt][2], acc[nt][3],
                     ah0, ah1, ah2, ah3, bl0, bl1);
            mma16816(acc[nt][0], acc[nt][1], acc[nt][2], acc[nt][3],
                     al0, al1, al2, al3, bh0, bh1);
        }
    }
    __syncwarp();   // all x reads done before aliasing overwrite below

    // scatter fragments into per-warp epi buffer (aliases own x region)
    float* epiw = (float*)(s_x + w * WREG);
#pragma unroll
    for (int nt = 0; nt < 8; ++nt) {
        const int c = nt * 8 + 2 * q;
        *(float2*)(epiw + g * 66 + c)       = make_float2(acc[nt][0], acc[nt][1]);
        *(float2*)(epiw + (g + 8) * 66 + c) = make_float2(acc[nt][2], acc[nt][3]);
    }
    __syncwarp();

    // per-edge epilogue: lane l owns cols 2l, 2l+1
    const float b0 = s_bias[2 * lane];
    const float b1 = s_bias[2 * lane + 1];
    const float a0 = s_attn[2 * lane];
    const float a1 = s_attn[2 * lane + 1];

    for (int r = 0; r < 16; ++r) {
        long long e_r = ewarp + r;
        if (e_r >= E) break;                    // warp-uniform
        const int s_r = __shfl_sync(0xffffffffu, myS, r);
        const int d_r = __shfl_sync(0xffffffffu, myD, r);

        float2 fa = *(const float2*)(g_fni + (size_t)s_r * 64 + 2 * lane);
        float2 fb = *(const float2*)(g_fnj + (size_t)d_r * 64 + 2 * lane);
        float2 ac = *(const float2*)(epiw + r * 66 + 2 * lane);

        float y0 = ac.x + fa.x + fb.x + b0;
        float y1 = ac.y + fa.y + fb.y + b1;
        y0 = (y0 > 0.0f) ? y0 : 0.01f * y0;
        y1 = (y1 > 0.0f) ? y1 : 0.01f * y1;

        float lp = y0 * a0 + y1 * a1;
        lp += __shfl_xor_sync(0xffffffffu, lp, 4);
        lp += __shfl_xor_sync(0xffffffffu, lp, 2);
        lp += __shfl_xor_sync(0xffffffffu, lp, 1);

        y0 += __shfl_xor_sync(0xffffffffu, y0, 8);
        y0 += __shfl_xor_sync(0xffffffffu, y0, 16);
        y1 += __shfl_xor_sync(0xffffffffu, y1, 8);
        y1 += __shfl_xor_sync(0xffffffffu, y1, 16);

        float l1v = __shfl_sync(0xffffffffu, lp, 8);
        float l2v = __shfl_sync(0xffffffffu, lp, 16);
        float l3v = __shfl_sync(0xffffffffu, lp, 24);

        if (lane < 8)
            *(float2*)(out_e + (size_t)e_r * 16 + 2 * lane) =
                make_float2(0.25f * y0, 0.25f * y1);

        if (lane == 0) {
            float e0 = expf(lp),  e1 = expf(l1v);
            float e2 = expf(l2v), e3 = expf(l3v);
            *(float4*)(g_ex + (size_t)e_r * 4) = make_float4(e0, e1, e2, e3);
            red_add_v4(&g_z[(size_t)d_r * 4], e0, e1, e2, e3);
        }
    }
}

// ---------------------------------------------------------------------------
// Kernel 3: invert z once per (node, head)
// ---------------------------------------------------------------------------
__global__ void inv_z(int N) {
    int i = blockIdx.x * 256 + threadIdx.x;
    if (i < N * 4) g_z[i] = __frcp_rn(g_z[i]);
}

// ---------------------------------------------------------------------------
// Kernel 4: edge pass 2.
// ---------------------------------------------------------------------------
__global__ __launch_bounds__(256)
void edge_aggr(const int* __restrict__ src,
               const int* __restrict__ dst,
               float* __restrict__ out_n,
               int E)
{
    const int tid  = threadIdx.x;
    const int lane = tid & 31;
    const int t    = lane & 7;
    const int le   = (tid >> 5) * 4 + (lane >> 3);
    const long long e = (long long)blockIdx.x * 32 + le;
    if (e >= E) return;

    const int s = src[e];
    const int d = dst[e];

    float4 ex4 = *(const float4*)(g_ex + (size_t)e * 4);
    float4 zi4 = *(const float4*)(g_z  + (size_t)d * 4);
    const float a0 = 0.25f * ex4.x * zi4.x;
    const float a1 = 0.25f * ex4.y * zi4.y;
    const float a2 = 0.25f * ex4.z * zi4.z;
    const float a3 = 0.25f * ex4.w * zi4.w;

    const float* hr = g_hsrc + (size_t)s * 64 + 2 * t;
    float2 v0 = *(const float2*)(hr);
    float2 v1 = *(const float2*)(hr + 16);
    float2 v2 = *(const float2*)(hr + 32);
    float2 v3 = *(const float2*)(hr + 48);

    float m0 = a0 * v0.x + a1 * v1.x + a2 * v2.x + a3 * v3.x;
    float m1 = a0 * v0.y + a1 * v1.y + a2 * v2.y + a3 * v3.y;

    red_add_v2(out_n + (size_t)d * 16 + 2 * t, m0, m1);
}

// ---------------------------------------------------------------------------
extern "C" void kernel_launch(void* const* d_in, const int* in_sizes, int n_in,
                              void* d_out, int out_size)
{
    const float* nfeats = (const float*)d_in[0];
    const float* efeats = (const float*)d_in[1];
    const int*   src    = (const int*)  d_in[2];
    const int*   dst    = (const int*)  d_in[3];
    const float* Wni    = (const float*)d_in[4];
    const float* Wnj    = (const float*)d_in[5];
    const float* Wfij   = (const float*)d_in[6];
    const float* Wsrc   = (const float*)d_in[7];
    const float* bsrc   = (const float*)d_in[8];
    const float* attn   = (const float*)d_in[9];
    const float* biase  = (const float*)d_in[10];

    const int N = in_sizes[0] / 128;
    const int E = in_sizes[2];

    float* out_n = (float*)d_out;
    float* out_e = out_n + (size_t)N * 16;

    static int smem_set = 0;
    const int EM_SMEM = (64 * WS * 2 + 8 * WREG + 128) * 4;  // 55808 B
    if (!smem_set) {
        cudaFuncSetAttribute(edge_main,
                             cudaFuncAttributeMaxDynamicSharedMemorySize,
                             EM_SMEM);
        smem_set = 1;
    }

    // launch order chosen so index 3 (the one ncu profiles) = edge_main
    zero_kernel<<<(N * 16 + 255) / 256, 256>>>(out_n, N);

    wsplit<<<8, 256>>>(Wfij);

    dim3 g1((N + 255) / 256, 3);
    node_gemm<<<g1, 256>>>(nfeats, Wni, Wnj, Wsrc, bsrc, N);

    edge_main<<<(E + 127) / 128, 256, EM_SMEM>>>(efeats, src, dst,
                                                 attn, biase, out_e, E);

    inv_z<<<(N * 4 + 255) / 256, 256>>>(N);

    edge_aggr<<<(E + 31) / 32, 256>>>(src, dst, out_n, E);
}